// round 4
// baseline (speedup 1.0000x reference)
#include <cuda_runtime.h>

// Problem constants (fixed by reference: B=32, C=2, H=512, W=512, L=3)
#define BB   32
#define HH   512
#define WW   512
#define LVAL 3.0f
#define ROWS_PER_BLOCK 8
#define NBLOCKS (HH / ROWS_PER_BLOCK * BB)

// Persistent scratch (allocation-free). Zero-initialized at module load;
// the last block resets it after each run so graph replays stay correct.
__device__ double g_part[BB];
__device__ unsigned int g_count = 0;

// Select 9 consecutive floats starting at warp-uniform phase o (0..3) from
// three aligned float4s.
__device__ __forceinline__ void sel9(const float4 A, const float4 B, const float4 C,
                                     const int o, float v[9]) {
    switch (o) {
    case 0:
        v[0]=A.x; v[1]=A.y; v[2]=A.z; v[3]=A.w;
        v[4]=B.x; v[5]=B.y; v[6]=B.z; v[7]=B.w; v[8]=C.x; break;
    case 1:
        v[0]=A.y; v[1]=A.z; v[2]=A.w; v[3]=B.x;
        v[4]=B.y; v[5]=B.z; v[6]=B.w; v[7]=C.x; v[8]=C.y; break;
    case 2:
        v[0]=A.z; v[1]=A.w; v[2]=B.x; v[3]=B.y;
        v[4]=B.z; v[5]=B.w; v[6]=C.x; v[7]=C.y; v[8]=C.z; break;
    default:
        v[0]=A.w; v[1]=B.x; v[2]=B.y; v[3]=B.z;
        v[4]=B.w; v[5]=C.x; v[6]=C.y; v[7]=C.z; v[8]=C.w; break;
    }
}

// Grid: (H/8, B). Block: 256 = 4 subrows x 64 chunk-threads.
// Thread (s, j) handles pixels x in [8j, 8j+8) of rows y = 8*bx + s + 4*it, it=0..1.
__global__ __launch_bounds__(256, 4) void symloss_kernel(
    const float* __restrict__ Flow,   // (B,2,H,W)
    const float* __restrict__ Asym,   // (B,2)
    const float* __restrict__ Bsym,   // (B,2)
    const float* __restrict__ Mask,   // (B,2,H,W)
    float* __restrict__ out)
{
    const int b  = blockIdx.y;
    const int s  = threadIdx.x >> 6;
    const int j  = threadIdx.x & 63;
    const int x0 = j << 3;
    const int ybase = blockIdx.x * ROWS_PER_BLOCK + s;

    const float a0 = Asym[2 * b];
    const float a1 = Asym[2 * b + 1];
    const float b0 = Bsym[2 * b];
    const float b1 = Bsym[2 * b + 1];

    const float dxs = -LVAL * a0;
    const float dys = fabsf(LVAL * a1);
    const float dy1 = floorf(dys);
    const float dx1 = floorf(dxs);
    const float fy  = dys - dy1;
    const float fx  = dxs - dx1;
    const int iy1 = (int)dy1;          // >= 0
    const int ix1 = (int)dx1;          // may be negative

    const int hp   = HH - 1 - iy1;
    const int x_lo = max(0, -ix1);
    const int x_hi = min(WW, WW - 1 - ix1);

    const float w11 = (1.f - fx) * (1.f - fy);
    const float w12 = fx * (1.f - fy);
    const float w21 = (1.f - fx) * fy;
    const float w22 = fx * fy;

    // Iteration-invariant chunk geometry.
    const int c0 = x0 + ix1;
    const int o  = c0 & 3;             // warp-uniform (x0 % 8 == 0)
    const int a  = c0 - o;             // 4-aligned
    const bool chunk_live = (x_hi > x_lo) && (x0 + 7 >= x_lo) && (x0 < x_hi);
    const bool fast = chunk_live && (a >= 0) && (a + 12 <= WW);

    float wv[8];                       // 0/1 per-pixel valid weights (iteration-invariant)
    #pragma unroll
    for (int i = 0; i < 8; i++) {
        const int x = x0 + i;
        wv[i] = ((x >= x_lo) && (x < x_hi)) ? 1.f : 0.f;
    }

    const float* f0 = Flow + ((size_t)(2 * b) * HH) * WW;
    const float* f1 = f0 + (size_t)HH * WW;
    const float* m0base = Mask + ((size_t)(2 * b) * HH) * WW;

    float sum = 0.f;

    #pragma unroll
    for (int it = 0; it < 2; it++) {
        const int y = ybase + 4 * it;
        if (!chunk_live || y >= hp) continue;

        const int r1 = y + iy1;        // <= H-2 for valid rows

        if (fast) {
            // ---- channel 0: two 9-wide shifted windows -> d0[8] ----
            const float* p0r1 = f0 + (size_t)r1 * WW + a;
            const float* p0r2 = p0r1 + WW;
            const float4 A0 = *(const float4*)(p0r1);
            const float4 B0 = *(const float4*)(p0r1 + 4);
            const float4 C0 = *(const float4*)(p0r1 + 8);
            const float4 A1 = *(const float4*)(p0r2);
            const float4 B1 = *(const float4*)(p0r2 + 4);
            const float4 C1 = *(const float4*)(p0r2 + 8);
            const float4 P0a = *(const float4*)(f0 + (size_t)y * WW + x0);
            const float4 P0b = *(const float4*)(f0 + (size_t)y * WW + x0 + 4);

            float va[9], vb[9];
            sel9(A0, B0, C0, o, va);   // flow0[r1][c0 .. c0+8]
            sel9(A1, B1, C1, o, vb);   // flow0[r2][c0 .. c0+8]

            const float P0[8] = {P0a.x, P0a.y, P0a.z, P0a.w, P0b.x, P0b.y, P0b.z, P0b.w};
            float d0[8];
            #pragma unroll
            for (int i = 0; i < 8; i++) {
                const float ph = w11 * va[i] + w12 * va[i + 1]
                               + w21 * vb[i] + w22 * vb[i + 1];
                d0[i] = P0[i] - ph;
            }

            // ---- channel 1 ----
            const float* p1r1 = f1 + (size_t)r1 * WW + a;
            const float* p1r2 = p1r1 + WW;
            const float4 A2 = *(const float4*)(p1r1);
            const float4 B2 = *(const float4*)(p1r1 + 4);
            const float4 C2 = *(const float4*)(p1r1 + 8);
            const float4 A3 = *(const float4*)(p1r2);
            const float4 B3 = *(const float4*)(p1r2 + 4);
            const float4 C3 = *(const float4*)(p1r2 + 8);
            const float4 P1a = *(const float4*)(f1 + (size_t)y * WW + x0);
            const float4 P1b = *(const float4*)(f1 + (size_t)y * WW + x0 + 4);

            sel9(A2, B2, C2, o, va);   // reuse va/vb registers
            sel9(A3, B3, C3, o, vb);

            const float P1[8] = {P1a.x, P1a.y, P1a.z, P1a.w, P1b.x, P1b.y, P1b.z, P1b.w};
            float sq[8];
            #pragma unroll
            for (int i = 0; i < 8; i++) {
                const float ph = w11 * va[i] + w12 * va[i + 1]
                               + w21 * vb[i] + w22 * vb[i + 1];
                const float d1 = P1[i] - ph;
                const float t  = d1 * b0 - d0[i] * b1;
                sq[i] = t * t;
            }

            // ---- masks last (independent stream) ----
            const float* m0 = m0base + (size_t)y * WW;
            const float4 M0a4 = *(const float4*)(m0 + x0);
            const float4 M0b4 = *(const float4*)(m0 + x0 + 4);
            const float4 M1a4 = *(const float4*)(m0 + (size_t)HH * WW + x0);
            const float4 M1b4 = *(const float4*)(m0 + (size_t)HH * WW + x0 + 4);
            const float M0[8] = {M0a4.x, M0a4.y, M0a4.z, M0a4.w, M0b4.x, M0b4.y, M0b4.z, M0b4.w};
            const float M1[8] = {M1a4.x, M1a4.y, M1a4.z, M1a4.w, M1b4.x, M1b4.y, M1b4.z, M1b4.w};

            #pragma unroll
            for (int i = 0; i < 8; i++)
                sum += (M0[i] + M1[i]) * wv[i] * sq[i];
        } else {
            // Edge chunk: scalar loads, only for valid pixels (c in [0, W-2]).
            const float* p0r1 = f0 + (size_t)r1 * WW;
            const float* p0r2 = p0r1 + WW;
            const float* p1r1 = f1 + (size_t)r1 * WW;
            const float* p1r2 = p1r1 + WW;
            const float* p0y  = f0 + (size_t)y * WW;
            const float* p1y  = f1 + (size_t)y * WW;
            const float* m0   = m0base + (size_t)y * WW;
            const float* m1   = m0 + (size_t)HH * WW;
            #pragma unroll
            for (int i = 0; i < 8; i++) {
                if (wv[i] == 0.f) continue;
                const int x = x0 + i;
                const int c = x + ix1;
                const float ph0 = w11 * p0r1[c] + w12 * p0r1[c + 1]
                                + w21 * p0r2[c] + w22 * p0r2[c + 1];
                const float ph1 = w11 * p1r1[c] + w12 * p1r1[c + 1]
                                + w21 * p1r2[c] + w22 * p1r2[c + 1];
                const float d0 = p0y[x] - ph0;
                const float d1 = p1y[x] - ph1;
                const float t  = d1 * b0 - d0 * b1;
                sum += (m0[x] + m1[x]) * (t * t);
            }
        }
    }

    // Block reduction: warp shuffle + shared.
    __shared__ float warp_sums[8];
    __shared__ bool  is_last;
    #pragma unroll
    for (int off = 16; off > 0; off >>= 1)
        sum += __shfl_down_sync(0xffffffffu, sum, off);

    const int lane = threadIdx.x & 31;
    const int wid  = threadIdx.x >> 5;
    if (lane == 0) warp_sums[wid] = sum;
    __syncthreads();

    if (threadIdx.x == 0) {
        float total = 0.f;
        #pragma unroll
        for (int w2 = 0; w2 < 8; w2++) total += warp_sums[w2];
        if (total != 0.f) {
            const float denom = 2.f * (float)max(hp, 1) * (float)max(x_hi - x_lo, 1);
            atomicAdd(&g_part[b], (double)(total / denom) * (1.0 / (double)BB));
        }
        __threadfence();
        const unsigned int prev = atomicAdd(&g_count, 1u);
        is_last = (prev == (unsigned int)(NBLOCKS - 1));
    }
    __syncthreads();

    // Last block finalizes and resets state for the next graph replay.
    if (is_last && threadIdx.x == 0) {
        double acc = 0.0;
        #pragma unroll
        for (int i = 0; i < BB; i++) {
            acc += g_part[i];
            g_part[i] = 0.0;
        }
        out[0] = (float)acc;
        __threadfence();
        g_count = 0;
    }
}

extern "C" void kernel_launch(void* const* d_in, const int* in_sizes, int n_in,
                              void* d_out, int out_size) {
    const float* Flow = (const float*)d_in[0];
    const float* Asym = (const float*)d_in[1];
    const float* Bsym = (const float*)d_in[2];
    const float* Mask = (const float*)d_in[3];
    float* out = (float*)d_out;

    dim3 grid(HH / ROWS_PER_BLOCK, BB);
    symloss_kernel<<<grid, 256>>>(Flow, Asym, Bsym, Mask, out);
}